// round 9
// baseline (speedup 1.0000x reference)
#include <cuda_runtime.h>
#include <cstdint>
#include <cstddef>

#define NN 100000
#define NE 640000
#define IN_CH 128
#define HID 256
#define OC 64

// ---------------- scratch ----------------
__device__ __align__(16) float g_cnt[NN];                     // inverse degree
__device__ __align__(16) int   g_deg[NN];                     // in-degree (int)
__device__ __align__(16) int   g_rowstart[NN + 1];            // CSR row offsets
__device__ __align__(16) int   g_cursor[NN];                  // fill cursors
__device__ __align__(16) int   g_esrc[NE];                    // CSR: src per slot
__device__ __align__(16) float g_agg1[(size_t)NN * IN_CH];    // sum of x over in-edges
__device__ __align__(16) float g_h[(size_t)NN * HID];         // layer-1 out (post ReLU)
__device__ __align__(16) float g_P[(size_t)NN * OC];          // h @ W2l^T

__device__ __forceinline__ int clampN(int v) {
    return ((unsigned)v < (unsigned)NN) ? v : 0;
}

// ---------------- tf32 helpers ----------------
__device__ __forceinline__ unsigned cvt_tf32(float f) {
    unsigned r;
    asm("cvt.rna.tf32.f32 %0, %1;" : "=r"(r) : "f"(f));
    return r;
}
__device__ __forceinline__ void mma_tf32(float* c, const unsigned* a, const unsigned* b) {
    asm volatile(
        "mma.sync.aligned.m16n8k8.row.col.f32.tf32.tf32.f32 "
        "{%0,%1,%2,%3}, {%4,%5,%6,%7}, {%8,%9}, {%0,%1,%2,%3};"
        : "+f"(c[0]), "+f"(c[1]), "+f"(c[2]), "+f"(c[3])
        : "r"(a[0]), "r"(a[1]), "r"(a[2]), "r"(a[3]), "r"(b[0]), "r"(b[1]));
}

// ---------------- CSR build ----------------
__global__ void zero_deg_kernel() {
    int i = blockIdx.x * blockDim.x + threadIdx.x;
    if (i < NN) g_deg[i] = 0;
}

__global__ void count_kernel(const int* __restrict__ ei) {
    int e = blockIdx.x * blockDim.x + threadIdx.x;
    if (e < NE) atomicAdd(&g_deg[clampN(ei[NE + e])], 1);
}

// single block, 1024 threads: chunked exclusive prefix sum of g_deg
__global__ void __launch_bounds__(1024) scan_kernel() {
    __shared__ int sh[1024];
    const int CH = (NN + 1023) / 1024;          // 98
    int t = threadIdx.x;
    int begin = t * CH;
    int end = begin + CH; if (end > NN) end = NN;
    int s = 0;
    for (int i = begin; i < end; i++) s += g_deg[i];
    sh[t] = s;
    __syncthreads();
    // Hillis-Steele inclusive scan
    for (int off = 1; off < 1024; off <<= 1) {
        int v = (t >= off) ? sh[t - off] : 0;
        __syncthreads();
        sh[t] += v;
        __syncthreads();
    }
    int run = sh[t] - s;                        // exclusive offset for this chunk
    for (int i = begin; i < end; i++) {
        g_rowstart[i] = run;
        g_cursor[i] = run;
        run += g_deg[i];
    }
    if (t == 1023) g_rowstart[NN] = sh[1023];
    // inverse degree while we're here (each thread covers its chunk)
    for (int i = begin; i < end; i++) {
        int d = g_deg[i];
        g_cnt[i] = 1.0f / (float)(d > 0 ? d : 1);
    }
}

__global__ void fill_kernel(const int* __restrict__ ei) {
    int e = blockIdx.x * blockDim.x + threadIdx.x;
    if (e >= NE) return;
    int s = clampN(ei[e]);
    int d = clampN(ei[NE + e]);
    int pos = atomicAdd(&g_cursor[d], 1);
    g_esrc[pos] = s;
}

// ---------------- gather1: agg1[n] = sum_{e in CSR(n)} x[src(e)]  (128 ch) ----------------
// one warp per node, float4 per lane.
__global__ void gather1_kernel(const float* __restrict__ x) {
    int gt = blockIdx.x * blockDim.x + threadIdx.x;
    int node = gt >> 5;
    int lane = gt & 31;
    if (node >= NN) return;
    int beg = g_rowstart[node];
    int end = g_rowstart[node + 1];
    float4 acc = make_float4(0.f, 0.f, 0.f, 0.f);
    const float4* x4 = (const float4*)x;
    for (int j = beg; j < end; j++) {
        int s = g_esrc[j];                       // broadcast load (L1)
        float4 v = x4[(size_t)s * 32 + lane];
        acc.x += v.x; acc.y += v.y; acc.z += v.z; acc.w += v.w;
    }
    ((float4*)g_agg1)[(size_t)node * 32 + lane] = acc;
}

// ---------------- gather2 + finalize: out[n] = outRaw[n] + inv*sum P[src] + b2 ----------------
// one warp per node, float2 per lane (64 ch).
__global__ void gather2_kernel(const float* __restrict__ b2,
                               float* __restrict__ out) {
    int gt = blockIdx.x * blockDim.x + threadIdx.x;
    int node = gt >> 5;
    int lane = gt & 31;
    if (node >= NN) return;
    int beg = g_rowstart[node];
    int end = g_rowstart[node + 1];
    float2 acc = make_float2(0.f, 0.f);
    const float2* P2 = (const float2*)g_P;
    for (int j = beg; j < end; j++) {
        int s = g_esrc[j];
        float2 v = P2[(size_t)s * 32 + lane];
        acc.x += v.x; acc.y += v.y;
    }
    float inv = g_cnt[node];
    size_t idx = (size_t)node * 32 + lane;       // float2 index
    float2 o = ((float2*)out)[idx];
    float2 bb = ((const float2*)b2)[lane];
    o.x += inv * acc.x + bb.x;
    o.y += inv * acc.y + bb.y;
    ((float2*)out)[idx] = o;
}

// ---------------- layer-1 tf32 tensor-core GEMM (unchanged from R8) ----------------
__global__ void __launch_bounds__(256)
gemm1_tf32(const float* __restrict__ x,
           const float* __restrict__ W1l,
           const float* __restrict__ W1r,
           const float* __restrict__ b1) {
    __shared__ unsigned As[128][36];
    __shared__ unsigned Bs[128][36];

    const int tid = threadIdx.x;
    const int lane = tid & 31;
    const int warp = tid >> 5;
    const int wm = warp >> 1;
    const int wn = warp & 1;
    const int rowBase = blockIdx.x * 128;
    const int colBase = blockIdx.y * 128;

    const int lr = tid >> 1;
    const int lc = (tid & 1) * 16;

    float acc[2][8][4];
#pragma unroll
    for (int mi = 0; mi < 2; mi++)
#pragma unroll
        for (int ni = 0; ni < 8; ni++)
#pragma unroll
            for (int t = 0; t < 4; t++) acc[mi][ni][t] = 0.0f;

#pragma unroll 1
    for (int kt = 0; kt < 8; kt++) {
        const bool first = kt < 4;
        const int koff = first ? kt * 32 : kt * 32 - 128;
        const float* Asrc = first ? g_agg1 : x;
        const float* Bsrc = first ? W1l : W1r;

        int n = rowBase + lr; if (n >= NN) n = NN - 1;
        const float* ap = Asrc + (size_t)n * IN_CH + koff + lc;
        const float s = first ? g_cnt[n] : 1.0f;
#pragma unroll
        for (int i = 0; i < 4; i++) {
            float4 v = *(const float4*)(ap + i * 4);
            uint4 t;
            t.x = cvt_tf32(v.x * s); t.y = cvt_tf32(v.y * s);
            t.z = cvt_tf32(v.z * s); t.w = cvt_tf32(v.w * s);
            *(uint4*)&As[lr][lc + i * 4] = t;
        }
        const float* bp = Bsrc + (size_t)(colBase + lr) * IN_CH + koff + lc;
#pragma unroll
        for (int i = 0; i < 4; i++) {
            float4 v = *(const float4*)(bp + i * 4);
            uint4 t;
            t.x = cvt_tf32(v.x); t.y = cvt_tf32(v.y);
            t.z = cvt_tf32(v.z); t.w = cvt_tf32(v.w);
            *(uint4*)&Bs[lr][lc + i * 4] = t;
        }
        __syncthreads();

#pragma unroll
        for (int kk = 0; kk < 4; kk++) {
            const int kc = kk * 8 + (lane & 3);
            unsigned a[2][4];
#pragma unroll
            for (int mi = 0; mi < 2; mi++) {
                int r0 = wm * 32 + mi * 16 + (lane >> 2);
                a[mi][0] = As[r0][kc];
                a[mi][1] = As[r0 + 8][kc];
                a[mi][2] = As[r0][kc + 4];
                a[mi][3] = As[r0 + 8][kc + 4];
            }
            unsigned bf[8][2];
#pragma unroll
            for (int ni = 0; ni < 8; ni++) {
                int c0 = wn * 64 + ni * 8 + (lane >> 2);
                bf[ni][0] = Bs[c0][kc];
                bf[ni][1] = Bs[c0][kc + 4];
            }
#pragma unroll
            for (int mi = 0; mi < 2; mi++)
#pragma unroll
                for (int ni = 0; ni < 8; ni++)
                    mma_tf32(acc[mi][ni], a[mi], bf[ni]);
        }
        __syncthreads();
    }

#pragma unroll
    for (int mi = 0; mi < 2; mi++) {
        int r0 = rowBase + wm * 32 + mi * 16 + (lane >> 2);
#pragma unroll
        for (int ni = 0; ni < 8; ni++) {
            int c = colBase + wn * 64 + ni * 8 + 2 * (lane & 3);
            float bb0 = b1[c], bb1 = b1[c + 1];
            if (r0 < NN) {
                float2 st;
                st.x = fmaxf(acc[mi][ni][0] + bb0, 0.0f);
                st.y = fmaxf(acc[mi][ni][1] + bb1, 0.0f);
                *(float2*)&g_h[(size_t)r0 * HID + c] = st;
            }
            int r1 = r0 + 8;
            if (r1 < NN) {
                float2 st;
                st.x = fmaxf(acc[mi][ni][2] + bb0, 0.0f);
                st.y = fmaxf(acc[mi][ni][3] + bb1, 0.0f);
                *(float2*)&g_h[(size_t)r1 * HID + c] = st;
            }
        }
    }
}

// ---------------- layer-2 tf32 GEMMs (unchanged from R8) ----------------
__global__ void __launch_bounds__(256)
gemm2_tf32(const float* __restrict__ W2l,
           const float* __restrict__ W2r,
           float* __restrict__ outRaw) {
    __shared__ unsigned As[128][36];
    __shared__ unsigned Bs[64][36];

    const float* W = (blockIdx.y == 0) ? W2l : W2r;
    float* C = (blockIdx.y == 0) ? g_P : outRaw;

    const int tid = threadIdx.x;
    const int lane = tid & 31;
    const int warp = tid >> 5;
    const int wm = warp >> 1;
    const int wn = warp & 1;
    const int rowBase = blockIdx.x * 128;

    const int lr = tid >> 1;
    const int lc = (tid & 1) * 16;
    const int br = tid >> 2;
    const int bc = (tid & 3) * 8;

    float acc[2][4][4];
#pragma unroll
    for (int mi = 0; mi < 2; mi++)
#pragma unroll
        for (int ni = 0; ni < 4; ni++)
#pragma unroll
            for (int t = 0; t < 4; t++) acc[mi][ni][t] = 0.0f;

#pragma unroll 1
    for (int kt = 0; kt < 8; kt++) {
        const int koff = kt * 32;
        int n = rowBase + lr; if (n >= NN) n = NN - 1;
        const float* ap = g_h + (size_t)n * HID + koff + lc;
#pragma unroll
        for (int i = 0; i < 4; i++) {
            float4 v = *(const float4*)(ap + i * 4);
            uint4 t;
            t.x = cvt_tf32(v.x); t.y = cvt_tf32(v.y);
            t.z = cvt_tf32(v.z); t.w = cvt_tf32(v.w);
            *(uint4*)&As[lr][lc + i * 4] = t;
        }
        const float* bp = W + (size_t)br * HID + koff + bc;
#pragma unroll
        for (int i = 0; i < 2; i++) {
            float4 v = *(const float4*)(bp + i * 4);
            uint4 t;
            t.x = cvt_tf32(v.x); t.y = cvt_tf32(v.y);
            t.z = cvt_tf32(v.z); t.w = cvt_tf32(v.w);
            *(uint4*)&Bs[br][bc + i * 4] = t;
        }
        __syncthreads();

#pragma unroll
        for (int kk = 0; kk < 4; kk++) {
            const int kc = kk * 8 + (lane & 3);
            unsigned a[2][4];
#pragma unroll
            for (int mi = 0; mi < 2; mi++) {
                int r0 = wm * 32 + mi * 16 + (lane >> 2);
                a[mi][0] = As[r0][kc];
                a[mi][1] = As[r0 + 8][kc];
                a[mi][2] = As[r0][kc + 4];
                a[mi][3] = As[r0 + 8][kc + 4];
            }
            unsigned bf[4][2];
#pragma unroll
            for (int ni = 0; ni < 4; ni++) {
                int c0 = wn * 32 + ni * 8 + (lane >> 2);
                bf[ni][0] = Bs[c0][kc];
                bf[ni][1] = Bs[c0][kc + 4];
            }
#pragma unroll
            for (int mi = 0; mi < 2; mi++)
#pragma unroll
                for (int ni = 0; ni < 4; ni++)
                    mma_tf32(acc[mi][ni], a[mi], bf[ni]);
        }
        __syncthreads();
    }

#pragma unroll
    for (int mi = 0; mi < 2; mi++) {
        int r0 = rowBase + wm * 32 + mi * 16 + (lane >> 2);
#pragma unroll
        for (int ni = 0; ni < 4; ni++) {
            int c = wn * 32 + ni * 8 + 2 * (lane & 3);
            if (r0 < NN) {
                float2 st; st.x = acc[mi][ni][0]; st.y = acc[mi][ni][1];
                *(float2*)&C[(size_t)r0 * OC + c] = st;
            }
            int r1 = r0 + 8;
            if (r1 < NN) {
                float2 st; st.x = acc[mi][ni][2]; st.y = acc[mi][ni][3];
                *(float2*)&C[(size_t)r1 * OC + c] = st;
            }
        }
    }
}

// ---------------- launch ----------------
extern "C" void kernel_launch(void* const* d_in, const int* in_sizes, int n_in,
                              void* d_out, int out_size) {
    const float* x   = (const float*)d_in[0];
    const int*   ei  = (const int*)d_in[1];      // int32
    const float* W1l = (const float*)d_in[2];
    const float* b1  = (const float*)d_in[3];
    const float* W1r = (const float*)d_in[4];
    const float* W2l = (const float*)d_in[5];
    const float* b2  = (const float*)d_in[6];
    const float* W2r = (const float*)d_in[7];
    float* out = (float*)d_out;

    // CSR build
    zero_deg_kernel<<<(NN + 255) / 256, 256>>>();
    count_kernel<<<(NE + 255) / 256, 256>>>(ei);
    scan_kernel<<<1, 1024>>>();
    fill_kernel<<<(NE + 255) / 256, 256>>>(ei);

    // layer-1 aggregation (gather, no atomics)
    gather1_kernel<<<(NN * 32 + 255) / 256, 256>>>(x);

    // h = relu([agg1*inv | x] @ [W1l | W1r]^T + b1)
    gemm1_tf32<<<dim3((NN + 127) / 128, 2), 256>>>(x, W1l, W1r, b1);

    // P = h @ W2l^T ; out_raw = h @ W2r^T
    gemm2_tf32<<<dim3((NN + 127) / 128, 2), 256>>>(W2l, W2r, out);

    // layer-2 aggregation + finalize fused
    gather2_kernel<<<(NN * 32 + 255) / 256, 256>>>(b2, out);
}

// round 10
// speedup vs baseline: 1.3842x; 1.3842x over previous
#include <cuda_runtime.h>
#include <cstdint>
#include <cstddef>

#define NN 100000
#define NE 640000
#define IN_CH 128
#define HID 256
#define OC 64

// ---------------- scratch ----------------
__device__ __align__(16) float g_cnt[NN];
__device__ __align__(16) float g_agg1[(size_t)NN * IN_CH];
__device__ __align__(16) float g_h[(size_t)NN * HID];
__device__ __align__(16) float g_P[(size_t)NN * OC];
__device__ __align__(16) float g_agg2[(size_t)NN * OC];

__device__ __forceinline__ int clampN(int v) {
    return ((unsigned)v < (unsigned)NN) ? v : 0;
}

// ---------------- tf32 helpers ----------------
__device__ __forceinline__ unsigned cvt_tf32(float f) {
    unsigned r;
    asm("cvt.rna.tf32.f32 %0, %1;" : "=r"(r) : "f"(f));
    return r;
}
__device__ __forceinline__ void mma_tf32(float* c, const unsigned* a, const unsigned* b) {
    asm volatile(
        "mma.sync.aligned.m16n8k8.row.col.f32.tf32.tf32.f32 "
        "{%0,%1,%2,%3}, {%4,%5,%6,%7}, {%8,%9}, {%0,%1,%2,%3};"
        : "+f"(c[0]), "+f"(c[1]), "+f"(c[2]), "+f"(c[3])
        : "r"(a[0]), "r"(a[1]), "r"(a[2]), "r"(a[3]), "r"(b[0]), "r"(b[1]));
}
__device__ __forceinline__ uint4 cvt4(float4 v, float s) {
    uint4 t;
    t.x = cvt_tf32(v.x * s); t.y = cvt_tf32(v.y * s);
    t.z = cvt_tf32(v.z * s); t.w = cvt_tf32(v.w * s);
    return t;
}

// ---------------- degree count + inverse ----------------
__global__ void count_kernel(const int* __restrict__ ei) {
    int e = blockIdx.x * blockDim.x + threadIdx.x;
    if (e < NE) atomicAdd(&g_cnt[clampN(ei[NE + e])], 1.0f);
}
__global__ void inv_kernel() {
    int i = blockIdx.x * blockDim.x + threadIdx.x;
    if (i < NN) g_cnt[i] = 1.0f / fmaxf(g_cnt[i], 1.0f);
}

// ---------------- scatters (vector RED, proven fastest in R8) ----------------
__global__ void scatter1_kernel(const int* __restrict__ ei,
                                const float* __restrict__ x) {
    constexpr int Q = IN_CH / 4;
    int gt = blockIdx.x * blockDim.x + threadIdx.x;
    int e = gt >> 5;
    int q = gt & 31;
    if (e >= NE) return;
    int s = clampN(ei[e]);
    int d = clampN(ei[NE + e]);
    float4 v = *((const float4*)x + (size_t)s * Q + q);
    atomicAdd((float4*)g_agg1 + (size_t)d * Q + q, v);
}
__global__ void scatter2_kernel(const int* __restrict__ ei) {
    constexpr int Q = OC / 4;
    int gt = blockIdx.x * blockDim.x + threadIdx.x;
    int e = gt >> 4;
    int q = gt & 15;
    if (e >= NE) return;
    int s = clampN(ei[e]);
    int d = clampN(ei[NE + e]);
    float4 v = *((const float4*)g_P + (size_t)s * Q + q);
    atomicAdd((float4*)g_agg2 + (size_t)d * Q + q, v);
}

// ---------------- layer-1 tf32 GEMM, double-buffered global loads ----------------
// h[n,c] = relu( mean[n,:].W1l[c,:] + x[n,:].W1r[c,:] + b1[c] );  concat-K (K=256).
// BM=128, BN=128 (grid.y=2), BK=32. 8 warps 4x2; warp tile 32x64.
__global__ void __launch_bounds__(256)
gemm1_tf32(const float* __restrict__ x,
           const float* __restrict__ W1l,
           const float* __restrict__ W1r,
           const float* __restrict__ b1) {
    __shared__ unsigned As[128][36];
    __shared__ unsigned Bs[128][36];

    const int tid = threadIdx.x;
    const int lane = tid & 31;
    const int warp = tid >> 5;
    const int wm = warp >> 1;
    const int wn = warp & 1;
    const int rowBase = blockIdx.x * 128;
    const int colBase = blockIdx.y * 128;

    const int lr = tid >> 1;
    const int lc = (tid & 1) * 16;

    int nA = rowBase + lr; if (nA >= NN) nA = NN - 1;
    const float scale0 = g_cnt[nA];               // used in kt<4 phase

    float4 pa[4], pb[4];
    float ps;

    auto loadTile = [&](int kt) {
        const bool first = kt < 4;
        const int koff = first ? kt * 32 : kt * 32 - 128;
        const float* ap = (first ? g_agg1 : x) + (size_t)nA * IN_CH + koff + lc;
        const float* bp = (first ? W1l : W1r) + (size_t)(colBase + lr) * IN_CH + koff + lc;
        ps = first ? scale0 : 1.0f;
#pragma unroll
        for (int i = 0; i < 4; i++) pa[i] = *(const float4*)(ap + i * 4);
#pragma unroll
        for (int i = 0; i < 4; i++) pb[i] = *(const float4*)(bp + i * 4);
    };

    float acc[2][8][4];
#pragma unroll
    for (int mi = 0; mi < 2; mi++)
#pragma unroll
        for (int ni = 0; ni < 8; ni++)
#pragma unroll
            for (int t = 0; t < 4; t++) acc[mi][ni][t] = 0.0f;

    loadTile(0);

#pragma unroll 1
    for (int kt = 0; kt < 8; kt++) {
        // commit prefetched tile to smem (with tf32 convert)
        float psl = ps;
#pragma unroll
        for (int i = 0; i < 4; i++) *(uint4*)&As[lr][lc + i * 4] = cvt4(pa[i], psl);
#pragma unroll
        for (int i = 0; i < 4; i++) *(uint4*)&Bs[lr][lc + i * 4] = cvt4(pb[i], 1.0f);
        __syncthreads();

        if (kt < 7) loadTile(kt + 1);             // overlap with mma below

#pragma unroll
        for (int kk = 0; kk < 4; kk++) {
            const int kc = kk * 8 + (lane & 3);
            unsigned a[2][4];
#pragma unroll
            for (int mi = 0; mi < 2; mi++) {
                int r0 = wm * 32 + mi * 16 + (lane >> 2);
                a[mi][0] = As[r0][kc];
                a[mi][1] = As[r0 + 8][kc];
                a[mi][2] = As[r0][kc + 4];
                a[mi][3] = As[r0 + 8][kc + 4];
            }
            unsigned bf[8][2];
#pragma unroll
            for (int ni = 0; ni < 8; ni++) {
                int c0 = wn * 64 + ni * 8 + (lane >> 2);
                bf[ni][0] = Bs[c0][kc];
                bf[ni][1] = Bs[c0][kc + 4];
            }
#pragma unroll
            for (int mi = 0; mi < 2; mi++)
#pragma unroll
                for (int ni = 0; ni < 8; ni++)
                    mma_tf32(acc[mi][ni], a[mi], bf[ni]);
        }
        __syncthreads();
    }

#pragma unroll
    for (int mi = 0; mi < 2; mi++) {
        int r0 = rowBase + wm * 32 + mi * 16 + (lane >> 2);
#pragma unroll
        for (int ni = 0; ni < 8; ni++) {
            int c = colBase + wn * 64 + ni * 8 + 2 * (lane & 3);
            float bb0 = b1[c], bb1 = b1[c + 1];
            if (r0 < NN) {
                float2 st;
                st.x = fmaxf(acc[mi][ni][0] + bb0, 0.0f);
                st.y = fmaxf(acc[mi][ni][1] + bb1, 0.0f);
                *(float2*)&g_h[(size_t)r0 * HID + c] = st;
            }
            int r1 = r0 + 8;
            if (r1 < NN) {
                float2 st;
                st.x = fmaxf(acc[mi][ni][2] + bb0, 0.0f);
                st.y = fmaxf(acc[mi][ni][3] + bb1, 0.0f);
                *(float2*)&g_h[(size_t)r1 * HID + c] = st;
            }
        }
    }
}

// ---------------- layer-2 tf32 GEMMs, double-buffered ----------------
// blockIdx.y==0: W2l -> g_P ; ==1: W2r -> out (raw; bias+mean added by finalize).
// BM=128, BN=64, BK=32. 8 warps 4x2; warp tile 32x32.
__global__ void __launch_bounds__(256)
gemm2_tf32(const float* __restrict__ W2l,
           const float* __restrict__ W2r,
           float* __restrict__ outRaw) {
    __shared__ unsigned As[128][36];
    __shared__ unsigned Bs[64][36];

    const float* W = (blockIdx.y == 0) ? W2l : W2r;
    float* C = (blockIdx.y == 0) ? g_P : outRaw;

    const int tid = threadIdx.x;
    const int lane = tid & 31;
    const int warp = tid >> 5;
    const int wm = warp >> 1;
    const int wn = warp & 1;
    const int rowBase = blockIdx.x * 128;

    const int lr = tid >> 1;
    const int lc = (tid & 1) * 16;
    const int br = tid >> 2;
    const int bc = (tid & 3) * 8;

    int nA = rowBase + lr; if (nA >= NN) nA = NN - 1;

    float4 pa[4], pb[2];
    auto loadTile = [&](int kt) {
        const int koff = kt * 32;
        const float* ap = g_h + (size_t)nA * HID + koff + lc;
        const float* bp = W + (size_t)br * HID + koff + bc;
#pragma unroll
        for (int i = 0; i < 4; i++) pa[i] = *(const float4*)(ap + i * 4);
#pragma unroll
        for (int i = 0; i < 2; i++) pb[i] = *(const float4*)(bp + i * 4);
    };

    float acc[2][4][4];
#pragma unroll
    for (int mi = 0; mi < 2; mi++)
#pragma unroll
        for (int ni = 0; ni < 4; ni++)
#pragma unroll
            for (int t = 0; t < 4; t++) acc[mi][ni][t] = 0.0f;

    loadTile(0);

#pragma unroll 1
    for (int kt = 0; kt < 8; kt++) {
#pragma unroll
        for (int i = 0; i < 4; i++) *(uint4*)&As[lr][lc + i * 4] = cvt4(pa[i], 1.0f);
#pragma unroll
        for (int i = 0; i < 2; i++) *(uint4*)&Bs[br][bc + i * 4] = cvt4(pb[i], 1.0f);
        __syncthreads();

        if (kt < 7) loadTile(kt + 1);

#pragma unroll
        for (int kk = 0; kk < 4; kk++) {
            const int kc = kk * 8 + (lane & 3);
            unsigned a[2][4];
#pragma unroll
            for (int mi = 0; mi < 2; mi++) {
                int r0 = wm * 32 + mi * 16 + (lane >> 2);
                a[mi][0] = As[r0][kc];
                a[mi][1] = As[r0 + 8][kc];
                a[mi][2] = As[r0][kc + 4];
                a[mi][3] = As[r0 + 8][kc + 4];
            }
            unsigned bf[4][2];
#pragma unroll
            for (int ni = 0; ni < 4; ni++) {
                int c0 = wn * 32 + ni * 8 + (lane >> 2);
                bf[ni][0] = Bs[c0][kc];
                bf[ni][1] = Bs[c0][kc + 4];
            }
#pragma unroll
            for (int mi = 0; mi < 2; mi++)
#pragma unroll
                for (int ni = 0; ni < 4; ni++)
                    mma_tf32(acc[mi][ni], a[mi], bf[ni]);
        }
        __syncthreads();
    }

#pragma unroll
    for (int mi = 0; mi < 2; mi++) {
        int r0 = rowBase + wm * 32 + mi * 16 + (lane >> 2);
#pragma unroll
        for (int ni = 0; ni < 4; ni++) {
            int c = wn * 32 + ni * 8 + 2 * (lane & 3);
            if (r0 < NN) {
                float2 st; st.x = acc[mi][ni][0]; st.y = acc[mi][ni][1];
                *(float2*)&C[(size_t)r0 * OC + c] = st;
            }
            int r1 = r0 + 8;
            if (r1 < NN) {
                float2 st; st.x = acc[mi][ni][2]; st.y = acc[mi][ni][3];
                *(float2*)&C[(size_t)r1 * OC + c] = st;
            }
        }
    }
}

// ---------------- finalize: out += inv * agg2 + b2 ----------------
__global__ void finalize_kernel(const float* __restrict__ b2,
                                float* __restrict__ out) {
    int i = blockIdx.x * blockDim.x + threadIdx.x;
    if (i >= NN * (OC / 4)) return;
    int n = i / (OC / 4);
    int c4 = i % (OC / 4);
    float inv = g_cnt[n];
    float4 o = ((float4*)out)[i];
    float4 a = ((const float4*)g_agg2)[i];
    float4 b = ((const float4*)b2)[c4];
    o.x += inv * a.x + b.x;
    o.y += inv * a.y + b.y;
    o.z += inv * a.z + b.z;
    o.w += inv * a.w + b.w;
    ((float4*)out)[i] = o;
}

// ---------------- launch ----------------
extern "C" void kernel_launch(void* const* d_in, const int* in_sizes, int n_in,
                              void* d_out, int out_size) {
    const float* x   = (const float*)d_in[0];
    const int*   ei  = (const int*)d_in[1];      // int32
    const float* W1l = (const float*)d_in[2];
    const float* b1  = (const float*)d_in[3];
    const float* W1r = (const float*)d_in[4];
    const float* W2l = (const float*)d_in[5];
    const float* b2  = (const float*)d_in[6];
    const float* W2r = (const float*)d_in[7];
    float* out = (float*)d_out;

    // async memsets (graph-capturable; proven in R6)
    void *p_cnt, *p_agg1, *p_agg2;
    cudaGetSymbolAddress(&p_cnt, g_cnt);
    cudaGetSymbolAddress(&p_agg1, g_agg1);
    cudaGetSymbolAddress(&p_agg2, g_agg2);
    cudaMemsetAsync(p_cnt, 0, (size_t)NN * sizeof(float));
    cudaMemsetAsync(p_agg1, 0, (size_t)NN * IN_CH * sizeof(float));
    cudaMemsetAsync(p_agg2, 0, (size_t)NN * OC * sizeof(float));

    count_kernel<<<(NE + 255) / 256, 256>>>(ei);
    inv_kernel<<<(NN + 255) / 256, 256>>>();

    scatter1_kernel<<<(NE * 32 + 255) / 256, 256>>>(ei, x);

    gemm1_tf32<<<dim3((NN + 127) / 128, 2), 256>>>(x, W1l, W1r, b1);

    gemm2_tf32<<<dim3((NN + 127) / 128, 2), 256>>>(W2l, W2r, out);

    scatter2_kernel<<<(NE * 16 + 255) / 256, 256>>>(ei);

    finalize_kernel<<<(NN * (OC / 4) + 255) / 256, 256>>>(b2, out);
}

// round 12
// speedup vs baseline: 1.3897x; 1.0040x over previous
#include <cuda_runtime.h>
#include <cstdint>
#include <cstddef>

#define NN 100000
#define NE 640000
#define IN_CH 128
#define HID 256
#define OC 64
#define SW 40   // smem row stride in words (mod 32 == 8 -> conflict-free LDS.64 frags)

// ---------------- scratch ----------------
__device__ __align__(16) float g_cnt[NN];
__device__ __align__(16) float g_agg1[(size_t)NN * IN_CH];
__device__ __align__(16) float g_h[(size_t)NN * HID];
__device__ __align__(16) float g_P[(size_t)NN * OC];
__device__ __align__(16) float g_agg2[(size_t)NN * OC];

__device__ __forceinline__ int clampN(int v) {
    return ((unsigned)v < (unsigned)NN) ? v : 0;
}

// ---------------- tf32 helpers ----------------
__device__ __forceinline__ unsigned cvt_tf32(float f) {
    unsigned r;
    asm("cvt.rna.tf32.f32 %0, %1;" : "=r"(r) : "f"(f));
    return r;
}
__device__ __forceinline__ void mma_tf32(float* c, const unsigned* a, const unsigned* b) {
    asm volatile(
        "mma.sync.aligned.m16n8k8.row.col.f32.tf32.tf32.f32 "
        "{%0,%1,%2,%3}, {%4,%5,%6,%7}, {%8,%9}, {%0,%1,%2,%3};"
        : "+f"(c[0]), "+f"(c[1]), "+f"(c[2]), "+f"(c[3])
        : "r"(a[0]), "r"(a[1]), "r"(a[2]), "r"(a[3]), "r"(b[0]), "r"(b[1]));
}

// Convert 16 k-consecutive floats and store pair-packed:
// within each 8-k group, order becomes {v0,v4,v1,v5,v2,v6,v3,v7} so that the
// fragment pair (k, k+4) sits in one 8-byte word -> LDS.64 fragment loads.
__device__ __forceinline__ void store_packed16(unsigned* rowptr, int lc,
                                               const float4* v4, float s) {
    unsigned t[16];
#pragma unroll
    for (int i = 0; i < 4; i++) {
        t[i * 4 + 0] = cvt_tf32(v4[i].x * s);
        t[i * 4 + 1] = cvt_tf32(v4[i].y * s);
        t[i * 4 + 2] = cvt_tf32(v4[i].z * s);
        t[i * 4 + 3] = cvt_tf32(v4[i].w * s);
    }
#pragma unroll
    for (int g = 0; g < 2; g++) {
        const unsigned* u = t + g * 8;
        uint4 w0 = make_uint4(u[0], u[4], u[1], u[5]);
        uint4 w1 = make_uint4(u[2], u[6], u[3], u[7]);
        *(uint4*)(rowptr + lc + g * 8)     = w0;
        *(uint4*)(rowptr + lc + g * 8 + 4) = w1;
    }
}

// ---------------- degree count + inverse ----------------
__global__ void count_kernel(const int* __restrict__ ei) {
    int e = blockIdx.x * blockDim.x + threadIdx.x;
    if (e < NE) atomicAdd(&g_cnt[clampN(ei[NE + e])], 1.0f);
}
__global__ void inv_kernel() {
    int i = blockIdx.x * blockDim.x + threadIdx.x;
    if (i < NN) g_cnt[i] = 1.0f / fmaxf(g_cnt[i], 1.0f);
}

// ---------------- scatters (vector RED, fastest known) ----------------
__global__ void scatter1_kernel(const int* __restrict__ ei,
                                const float* __restrict__ x) {
    constexpr int Q = IN_CH / 4;
    int gt = blockIdx.x * blockDim.x + threadIdx.x;
    int e = gt >> 5;
    int q = gt & 31;
    if (e >= NE) return;
    int s = clampN(ei[e]);
    int d = clampN(ei[NE + e]);
    float4 v = *((const float4*)x + (size_t)s * Q + q);
    atomicAdd((float4*)g_agg1 + (size_t)d * Q + q, v);
}
__global__ void scatter2_kernel(const int* __restrict__ ei) {
    constexpr int Q = OC / 4;
    int gt = blockIdx.x * blockDim.x + threadIdx.x;
    int e = gt >> 4;
    int q = gt & 15;
    if (e >= NE) return;
    int s = clampN(ei[e]);
    int d = clampN(ei[NE + e]);
    float4 v = *((const float4*)g_P + (size_t)s * Q + q);
    atomicAdd((float4*)g_agg2 + (size_t)d * Q + q, v);
}

// ---------------- layer-1 tf32 GEMM ----------------
// h[n,c] = relu( mean[n,:].W1l[c,:] + x[n,:].W1r[c,:] + b1[c] );  concat-K=256.
// BM=128, BN=128 (grid.y=2), BK=32. 8 warps 4x2; warp tile 32x64.
__global__ void __launch_bounds__(256, 2)
gemm1_tf32(const float* __restrict__ x,
           const float* __restrict__ W1l,
           const float* __restrict__ W1r,
           const float* __restrict__ b1) {
    __shared__ __align__(16) unsigned As[128][SW];
    __shared__ __align__(16) unsigned Bs[128][SW];

    const int tid = threadIdx.x;
    const int lane = tid & 31;
    const int warp = tid >> 5;
    const int wm = warp >> 1;
    const int wn = warp & 1;
    const int rowBase = blockIdx.x * 128;
    const int colBase = blockIdx.y * 128;

    const int lr = tid >> 1;
    const int lc = (tid & 1) * 16;

    int nA = rowBase + lr; if (nA >= NN) nA = NN - 1;
    const float scale0 = g_cnt[nA];

    float acc[2][8][4];
#pragma unroll
    for (int mi = 0; mi < 2; mi++)
#pragma unroll
        for (int ni = 0; ni < 8; ni++)
#pragma unroll
            for (int t = 0; t < 4; t++) acc[mi][ni][t] = 0.0f;

#pragma unroll 1
    for (int kt = 0; kt < 8; kt++) {
        const bool first = kt < 4;
        const int koff = first ? kt * 32 : kt * 32 - 128;
        const float* ap = (first ? g_agg1 : x) + (size_t)nA * IN_CH + koff + lc;
        const float* bp = (first ? W1l : W1r) + (size_t)(colBase + lr) * IN_CH + koff + lc;
        const float s = first ? scale0 : 1.0f;

        float4 va[4], vb[4];
#pragma unroll
        for (int i = 0; i < 4; i++) va[i] = *(const float4*)(ap + i * 4);
#pragma unroll
        for (int i = 0; i < 4; i++) vb[i] = *(const float4*)(bp + i * 4);
        store_packed16(As[lr], lc, va, s);
        store_packed16(Bs[lr], lc, vb, 1.0f);
        __syncthreads();

#pragma unroll
        for (int kk = 0; kk < 4; kk++) {
            const int kc2 = kk * 8 + (lane & 3) * 2;
            unsigned a[2][4];
#pragma unroll
            for (int mi = 0; mi < 2; mi++) {
                int r0 = wm * 32 + mi * 16 + (lane >> 2);
                uint2 lo = *(const uint2*)&As[r0][kc2];       // {A[kc], A[kc+4]}
                uint2 hi = *(const uint2*)&As[r0 + 8][kc2];
                a[mi][0] = lo.x; a[mi][1] = hi.x; a[mi][2] = lo.y; a[mi][3] = hi.y;
            }
            unsigned bf[8][2];
#pragma unroll
            for (int ni = 0; ni < 8; ni++) {
                int c0 = wn * 64 + ni * 8 + (lane >> 2);
                uint2 bb = *(const uint2*)&Bs[c0][kc2];
                bf[ni][0] = bb.x; bf[ni][1] = bb.y;
            }
#pragma unroll
            for (int mi = 0; mi < 2; mi++)
#pragma unroll
                for (int ni = 0; ni < 8; ni++)
                    mma_tf32(acc[mi][ni], a[mi], bf[ni]);
        }
        __syncthreads();
    }

#pragma unroll
    for (int mi = 0; mi < 2; mi++) {
        int r0 = rowBase + wm * 32 + mi * 16 + (lane >> 2);
#pragma unroll
        for (int ni = 0; ni < 8; ni++) {
            int c = colBase + wn * 64 + ni * 8 + 2 * (lane & 3);
            float bb0 = b1[c], bb1 = b1[c + 1];
            if (r0 < NN) {
                float2 st;
                st.x = fmaxf(acc[mi][ni][0] + bb0, 0.0f);
                st.y = fmaxf(acc[mi][ni][1] + bb1, 0.0f);
                *(float2*)&g_h[(size_t)r0 * HID + c] = st;
            }
            int r1 = r0 + 8;
            if (r1 < NN) {
                float2 st;
                st.x = fmaxf(acc[mi][ni][2] + bb0, 0.0f);
                st.y = fmaxf(acc[mi][ni][3] + bb1, 0.0f);
                *(float2*)&g_h[(size_t)r1 * HID + c] = st;
            }
        }
    }
}

// ---------------- layer-2 tf32 GEMMs ----------------
// blockIdx.y==0: W2l -> g_P ; ==1: W2r -> out (raw).
// BM=128, BN=64, BK=32. 8 warps 4x2; warp tile 32x32.
__global__ void __launch_bounds__(256, 2)
gemm2_tf32(const float* __restrict__ W2l,
           const float* __restrict__ W2r,
           float* __restrict__ outRaw) {
    __shared__ __align__(16) unsigned As[128][SW];
    __shared__ __align__(16) unsigned Bs[64][SW];

    const float* W = (blockIdx.y == 0) ? W2l : W2r;
    float* C = (blockIdx.y == 0) ? g_P : outRaw;

    const int tid = threadIdx.x;
    const int lane = tid & 31;
    const int warp = tid >> 5;
    const int wm = warp >> 1;
    const int wn = warp & 1;
    const int rowBase = blockIdx.x * 128;

    const int lr = tid >> 1;
    const int lc = (tid & 1) * 16;
    const int br = tid >> 2;              // B rows 0..63, 4 threads/row
    const int bc = (tid & 3) * 8;         // 8 k-values per thread

    int nA = rowBase + lr; if (nA >= NN) nA = NN - 1;

    float acc[2][4][4];
#pragma unroll
    for (int mi = 0; mi < 2; mi++)
#pragma unroll
        for (int ni = 0; ni < 4; ni++)
#pragma unroll
            for (int t = 0; t < 4; t++) acc[mi][ni][t] = 0.0f;

#pragma unroll 1
    for (int kt = 0; kt < 8; kt++) {
        const int koff = kt * 32;
        const float* ap = g_h + (size_t)nA * HID + koff + lc;
        float4 va[4];
#pragma unroll
        for (int i = 0; i < 4; i++) va[i] = *(const float4*)(ap + i * 4);
        store_packed16(As[lr], lc, va, 1.0f);

        // B: 8 k-values -> one packed group
        {
            const float* bp = W + (size_t)br * HID + koff + bc;
            float4 v0 = *(const float4*)(bp);
            float4 v1 = *(const float4*)(bp + 4);
            unsigned u[8];
            u[0] = cvt_tf32(v0.x); u[1] = cvt_tf32(v0.y);
            u[2] = cvt_tf32(v0.z); u[3] = cvt_tf32(v0.w);
            u[4] = cvt_tf32(v1.x); u[5] = cvt_tf32(v1.y);
            u[6] = cvt_tf32(v1.z); u[7] = cvt_tf32(v1.w);
            uint4 w0 = make_uint4(u[0], u[4], u[1], u[5]);
            uint4 w1 = make_uint4(u[2], u[6], u[3], u[7]);
            *(uint4*)(Bs[br] + bc)     = w0;
            *(uint4*)(Bs[br] + bc + 4) = w1;
        }
        __syncthreads();

#pragma unroll
        for (int kk = 0; kk < 4; kk++) {
            const int kc2 = kk * 8 + (lane & 3) * 2;
            unsigned a[2][4];
#pragma unroll
            for (int mi = 0; mi < 2; mi++) {
                int r0 = wm * 32 + mi * 16 + (lane >> 2);
                uint2 lo = *(const uint2*)&As[r0][kc2];
                uint2 hi = *(const uint2*)&As[r0 + 8][kc2];
                a[mi][0] = lo.x; a[mi][1] = hi.x; a[mi][2] = lo.y; a[mi][3] = hi.y;
            }
            unsigned bf[4][2];
#pragma unroll
            for (int ni = 0; ni < 4; ni++) {
                int c0 = wn * 32 + ni * 8 + (lane >> 2);
                uint2 bb = *(const uint2*)&Bs[c0][kc2];
                bf[ni][0] = bb.x; bf[ni][1] = bb.y;
            }
#pragma unroll
            for (int mi = 0; mi < 2; mi++)
#pragma unroll
                for (int ni = 0; ni < 4; ni++)
                    mma_tf32(acc[mi][ni], a[mi], bf[ni]);
        }
        __syncthreads();
    }

#pragma unroll
    for (int mi = 0; mi < 2; mi++) {
        int r0 = rowBase + wm * 32 + mi * 16 + (lane >> 2);
#pragma unroll
        for (int ni = 0; ni < 4; ni++) {
            int c = wn * 32 + ni * 8 + 2 * (lane & 3);
            if (r0 < NN) {
                float2 st; st.x = acc[mi][ni][0]; st.y = acc[mi][ni][1];
                *(float2*)&C[(size_t)r0 * OC + c] = st;
            }
            int r1 = r0 + 8;
            if (r1 < NN) {
                float2 st; st.x = acc[mi][ni][2]; st.y = acc[mi][ni][3];
                *(float2*)&C[(size_t)r1 * OC + c] = st;
            }
        }
    }
}

// ---------------- finalize: out += inv * agg2 + b2 ----------------
__global__ void finalize_kernel(const float* __restrict__ b2,
                                float* __restrict__ out) {
    int i = blockIdx.x * blockDim.x + threadIdx.x;
    if (i >= NN * (OC / 4)) return;
    int n = i / (OC / 4);
    int c4 = i % (OC / 4);
    float inv = g_cnt[n];
    float4 o = ((float4*)out)[i];
    float4 a = ((const float4*)g_agg2)[i];
    float4 b = ((const float4*)b2)[c4];
    o.x += inv * a.x + b.x;
    o.y += inv * a.y + b.y;
    o.z += inv * a.z + b.z;
    o.w += inv * a.w + b.w;
    ((float4*)out)[i] = o;
}

// ---------------- launch ----------------
extern "C" void kernel_launch(void* const* d_in, const int* in_sizes, int n_in,
                              void* d_out, int out_size) {
    const float* x   = (const float*)d_in[0];
    const int*   ei  = (const int*)d_in[1];      // int32
    const float* W1l = (const float*)d_in[2];
    const float* b1  = (const float*)d_in[3];
    const float* W1r = (const float*)d_in[4];
    const float* W2l = (const float*)d_in[5];
    const float* b2  = (const float*)d_in[6];
    const float* W2r = (const float*)d_in[7];
    float* out = (float*)d_out;

    void *p_cnt, *p_agg1, *p_agg2;
    cudaGetSymbolAddress(&p_cnt, g_cnt);
    cudaGetSymbolAddress(&p_agg1, g_agg1);
    cudaGetSymbolAddress(&p_agg2, g_agg2);
    cudaMemsetAsync(p_cnt, 0, (size_t)NN * sizeof(float));
    cudaMemsetAsync(p_agg1, 0, (size_t)NN * IN_CH * sizeof(float));
    cudaMemsetAsync(p_agg2, 0, (size_t)NN * OC * sizeof(float));

    count_kernel<<<(NE + 255) / 256, 256>>>(ei);
    inv_kernel<<<(NN + 255) / 256, 256>>>();

    scatter1_kernel<<<(NE * 32 + 255) / 256, 256>>>(ei, x);

    gemm1_tf32<<<dim3((NN + 127) / 128, 2), 256>>>(x, W1l, W1r, b1);

    gemm2_tf32<<<dim3((NN + 127) / 128, 2), 256>>>(W2l, W2r, out);

    scatter2_kernel<<<(NE * 16 + 255) / 256, 256>>>(ei);

    finalize_kernel<<<(NN * (OC / 4) + 255) / 256, 256>>>(b2, out);
}